// round 4
// baseline (speedup 1.0000x reference)
#include <cuda_runtime.h>
#include <cstdint>

#define HH 512
#define WW 512
#define GG 83
#define KK 12
#define NB 8
#define NF (2*(GG-1)*(GG-1))      /* 13448 faces */
#define NV (GG*GG)                /* 6889 verts  */
#define FRAGS (KK*KK)             /* 144         */
#define NFACE (NB*NF)             /* 107,584     */
#define TOTFRAG (NFACE*FRAGS)     /* 15,492,096  */
#define NPIX (NB*HH*WW)           /* 2,097,152   */

struct __align__(16) FaceRec {
    float x0, y0, x1, y1;
    float x2, y2, z0, z1;
    float z2, area; int bcx, bcy;
    int i0, i1, i2, valid;
};

__device__ FaceRec g_rec[NFACE];
__device__ unsigned long long g_zkey[NPIX];

// XLA:GPU-style f32 division (NVPTX div.full: fast, ~2ulp, sign-correct)
__device__ __forceinline__ float div_full(float a, float b) {
    float r;
    asm("div.full.f32 %0, %1, %2;" : "=f"(r) : "f"(a), "f"(b));
    return r;
}

// Unfused a*b - c*d, exactly as jnp elementwise ops evaluate (no contraction)
__device__ __forceinline__ float edge_fn(float ax, float ay, float bx, float by) {
    return __fsub_rn(__fmul_rn(ax, ay), __fmul_rn(bx, by));
}

// Unfused w0*a + w1*b + w2*c, left-associated like the Python expression
__device__ __forceinline__ float lerp3(float w0, float a, float w1, float b,
                                       float w2, float c) {
    return __fadd_rn(__fadd_rn(__fmul_rn(w0, a), __fmul_rn(w1, b)),
                     __fmul_rn(w2, c));
}

__global__ void init_kernel() {
    int i = blockIdx.x * blockDim.x + threadIdx.x;
    if (i < NPIX) g_zkey[i] = 0xFFFFFFFFFFFFFFFFULL;
}

__global__ void setup_kernel(const float* __restrict__ verts,
                             const int*   __restrict__ faces) {
    int idx = blockIdx.x * blockDim.x + threadIdx.x;
    if (idx >= NFACE) return;
    int n = idx / NF;
    int f = idx - n * NF;

    int i0 = faces[3*f + 0];
    int i1 = faces[3*f + 1];
    int i2 = faces[3*f + 2];

    const float* vb = verts + (size_t)n * NV * 3;
    float z0 = vb[3*i0+2], z1 = vb[3*i1+2], z2 = vb[3*i2+2];

    // Projection with div.full, matching XLA:GPU's p = v[:,:2] / z
    float x0 = div_full(vb[3*i0+0], z0), y0 = div_full(vb[3*i0+1], z0);
    float x1 = div_full(vb[3*i1+0], z1), y1 = div_full(vb[3*i1+1], z1);
    float x2 = div_full(vb[3*i2+0], z2), y2 = div_full(vb[3*i2+1], z2);

    float minx = floorf(fminf(fminf(x0, x1), x2));
    float miny = floorf(fminf(fminf(y0, y1), y2));
    int bcx = (int)fminf(fmaxf(minx, 0.f), (float)(WW - KK));
    int bcy = (int)fminf(fmaxf(miny, 0.f), (float)(HH - KK));

    float area = edge_fn(__fsub_rn(x1,x0), __fsub_rn(y2,y0),
                         __fsub_rn(y1,y0), __fsub_rn(x2,x0));

    bool front = (z0 > 0.f && z1 > 0.f && z2 > 0.f);
    bool valid = front && (fabsf(area) > 1e-9f);

    FaceRec rec;
    rec.x0 = x0; rec.y0 = y0; rec.x1 = x1; rec.y1 = y1;
    rec.x2 = x2; rec.y2 = y2;
    rec.z0 = z0; rec.z1 = z1; rec.z2 = z2;
    rec.area = area;
    rec.bcx = bcx; rec.bcy = bcy;
    rec.i0 = i0; rec.i1 = i1; rec.i2 = i2;
    rec.valid = valid ? 1 : 0;
    g_rec[idx] = rec;
}

__global__ void raster_kernel() {
    int idx = blockIdx.x * blockDim.x + threadIdx.x;
    if (idx >= TOTFRAG) return;

    int face = idx / FRAGS;
    int rem  = idx - face * FRAGS;
    int ky = rem / KK;
    int kx = rem - ky * KK;

    FaceRec rec = g_rec[face];
    if (!rec.valid) return;

    int n = face / NF;
    int r = (face - n * NF) * FRAGS + rem;     // cand index within batch

    int px = rec.bcx + kx;
    int py = rec.bcy + ky;
    float pxf = (float)px;
    float pyf = (float)py;

    float c0 = edge_fn(__fsub_rn(rec.x2,rec.x1), __fsub_rn(pyf,rec.y1),
                       __fsub_rn(rec.y2,rec.y1), __fsub_rn(pxf,rec.x1));
    float c1 = edge_fn(__fsub_rn(rec.x0,rec.x2), __fsub_rn(pyf,rec.y2),
                       __fsub_rn(rec.y0,rec.y2), __fsub_rn(pxf,rec.x2));

    float w0 = div_full(c0, rec.area);
    float w1 = div_full(c1, rec.area);
    float w2 = __fsub_rn(__fsub_rn(1.0f, w0), w1);

    if (!(w0 >= 0.f && w1 >= 0.f && w2 >= 0.f)) return;

    float depth = lerp3(w0, rec.z0, w1, rec.z1, w2, rec.z2);

    unsigned long long key =
        ((unsigned long long)__float_as_uint(depth) << 32) | (unsigned int)r;
    atomicMin(&g_zkey[n * (HH*WW) + py * WW + px], key);
}

__global__ void resolve_kernel(const float* __restrict__ vals,
                               float* __restrict__ out) {
    int i = blockIdx.x * blockDim.x + threadIdx.x;
    if (i >= NPIX) return;

    int n = i / (HH*WW);
    int p = i - n * (HH*WW);

    unsigned long long key = g_zkey[i];
    float u = 0.f, v = 0.f;
    bool has = (key != 0xFFFFFFFFFFFFFFFFULL);

    if (has) {
        int r   = (int)(key & 0xFFFFFFFFu);
        int f   = r / FRAGS;
        int rem = r - f * FRAGS;
        int ky  = rem / KK;
        int kx  = rem - ky * KK;

        FaceRec rec = g_rec[n * NF + f];

        float pxf = (float)(rec.bcx + kx);
        float pyf = (float)(rec.bcy + ky);

        float c0 = edge_fn(__fsub_rn(rec.x2,rec.x1), __fsub_rn(pyf,rec.y1),
                           __fsub_rn(rec.y2,rec.y1), __fsub_rn(pxf,rec.x1));
        float c1 = edge_fn(__fsub_rn(rec.x0,rec.x2), __fsub_rn(pyf,rec.y2),
                           __fsub_rn(rec.y0,rec.y2), __fsub_rn(pxf,rec.x2));

        float w0 = div_full(c0, rec.area);
        float w1 = div_full(c1, rec.area);
        float w2 = __fsub_rn(__fsub_rn(1.0f, w0), w1);

        u = lerp3(w0, vals[2*rec.i0+0], w1, vals[2*rec.i1+0], w2, vals[2*rec.i2+0]);
        v = lerp3(w0, vals[2*rec.i0+1], w1, vals[2*rec.i1+1], w2, vals[2*rec.i2+1]);
    }

    float mask = (has && (u > 0.f || v > 0.f)) ? 1.0f : 0.0f;

    float ou, ov;
    if (mask > 0.f) {
        ou = __fsub_rn(__fmul_rn(u, 2.0f), 1.0f);
        ov = __fsub_rn(__fmul_rn(v, 2.0f), 1.0f);
    } else {
        ou = -10.0f;
        ov = -10.0f;
    }

    size_t hw = (size_t)HH * WW;
    out[((size_t)n * 2 + 0) * hw + p] = ou;
    out[((size_t)n * 2 + 1) * hw + p] = ov;
    out[(size_t)NB * 2 * hw + (size_t)n * hw + p] = mask;
}

extern "C" void kernel_launch(void* const* d_in, const int* in_sizes, int n_in,
                              void* d_out, int out_size) {
    const float* verts = (const float*)d_in[0];
    const int*   faces = (const int*)d_in[1];
    const float* vals  = (const float*)d_in[2];
    float* out = (float*)d_out;

    init_kernel<<<(NPIX + 255) / 256, 256>>>();
    setup_kernel<<<(NFACE + 255) / 256, 256>>>(verts, faces);
    raster_kernel<<<(TOTFRAG + 255) / 256, 256>>>();
    resolve_kernel<<<(NPIX + 255) / 256, 256>>>(vals, out);
}

// round 5
// speedup vs baseline: 1.3625x; 1.3625x over previous
#include <cuda_runtime.h>
#include <cstdint>

#define HH 512
#define WW 512
#define GG 83
#define KK 12
#define NB 8
#define NF (2*(GG-1)*(GG-1))      /* 13448 faces */
#define NV (GG*GG)                /* 6889 verts  */
#define FRAGS (KK*KK)             /* 144         */
#define NFACE (NB*NF)             /* 107,584     */
#define NPIX (NB*HH*WW)           /* 2,097,152   */

/* raster threads: 4 pixels each -> 36 threads/face */
#define TPF 36
#define RTHREADS (NFACE*TPF)      /* 3,873,024 */

struct __align__(16) RRec {
    float A0, B0, x1, y1;    /* c0 = A0*(py-y1) - B0*(px-x1), A0=x2-x1, B0=y2-y1 */
    float A1, B1, x2, y2;    /* c1 = A1*(py-y2) - B1*(px-x2), A1=x0-x2, B1=y0-y2 */
    float area, z0, z1, z2;
    int bcx, bcy, valid, pad;
};

struct __align__(16) UVRec {
    float u0, v0, u1, v1;
    float u2, v2, p0, p1;
};

__device__ RRec  g_rrec[NFACE];
__device__ UVRec g_uv[NFACE];
__device__ unsigned long long g_zkey[NPIX];

/* XLA:GPU f32 division (NVPTX div.full: fast, ~2ulp, sign-correct) */
__device__ __forceinline__ float div_full(float a, float b) {
    float r;
    asm("div.full.f32 %0, %1, %2;" : "=f"(r) : "f"(a), "f"(b));
    return r;
}

/* Unfused a*b - c*d, matching jnp elementwise evaluation */
__device__ __forceinline__ float edge_fn(float ax, float ay, float bx, float by) {
    return __fsub_rn(__fmul_rn(ax, ay), __fmul_rn(bx, by));
}

/* Unfused w0*a + w1*b + w2*c, left-associated */
__device__ __forceinline__ float lerp3(float w0, float a, float w1, float b,
                                       float w2, float c) {
    return __fadd_rn(__fadd_rn(__fmul_rn(w0, a), __fmul_rn(w1, b)),
                     __fmul_rn(w2, c));
}

__global__ void init_kernel() {
    int i = blockIdx.x * blockDim.x + threadIdx.x;
    if (i < NPIX / 2) {
        ((ulonglong2*)g_zkey)[i] =
            make_ulonglong2(0xFFFFFFFFFFFFFFFFULL, 0xFFFFFFFFFFFFFFFFULL);
    }
}

__global__ void setup_kernel(const float* __restrict__ verts,
                             const int*   __restrict__ faces,
                             const float* __restrict__ vals) {
    int idx = blockIdx.x * blockDim.x + threadIdx.x;
    if (idx >= NFACE) return;
    int n = idx / NF;
    int f = idx - n * NF;

    int i0 = faces[3*f + 0];
    int i1 = faces[3*f + 1];
    int i2 = faces[3*f + 2];

    const float* vb = verts + (size_t)n * NV * 3;
    float z0 = vb[3*i0+2], z1 = vb[3*i1+2], z2 = vb[3*i2+2];

    /* projection via div.full, matching XLA:GPU p = v[:,:2] / z */
    float x0 = div_full(vb[3*i0+0], z0), y0 = div_full(vb[3*i0+1], z0);
    float x1 = div_full(vb[3*i1+0], z1), y1 = div_full(vb[3*i1+1], z1);
    float x2 = div_full(vb[3*i2+0], z2), y2 = div_full(vb[3*i2+1], z2);

    float minx = floorf(fminf(fminf(x0, x1), x2));
    float miny = floorf(fminf(fminf(y0, y1), y2));
    int bcx = (int)fminf(fmaxf(minx, 0.f), (float)(WW - KK));
    int bcy = (int)fminf(fmaxf(miny, 0.f), (float)(HH - KK));

    float area = edge_fn(__fsub_rn(x1,x0), __fsub_rn(y2,y0),
                         __fsub_rn(y1,y0), __fsub_rn(x2,x0));

    bool front = (z0 > 0.f && z1 > 0.f && z2 > 0.f);
    bool valid = front && (fabsf(area) > 1e-9f);

    RRec rec;
    rec.A0 = __fsub_rn(x2, x1); rec.B0 = __fsub_rn(y2, y1);
    rec.x1 = x1; rec.y1 = y1;
    rec.A1 = __fsub_rn(x0, x2); rec.B1 = __fsub_rn(y0, y2);
    rec.x2 = x2; rec.y2 = y2;
    rec.area = area;
    rec.z0 = z0; rec.z1 = z1; rec.z2 = z2;
    rec.bcx = bcx; rec.bcy = bcy;
    rec.valid = valid ? 1 : 0;
    rec.pad = 0;
    g_rrec[idx] = rec;

    UVRec uv;
    uv.u0 = vals[2*i0+0]; uv.v0 = vals[2*i0+1];
    uv.u1 = vals[2*i1+0]; uv.v1 = vals[2*i1+1];
    uv.u2 = vals[2*i2+0]; uv.v2 = vals[2*i2+1];
    uv.p0 = 0.f; uv.p1 = 0.f;
    g_uv[idx] = uv;
}

__global__ void __launch_bounds__(256) raster_kernel() {
    int idx = blockIdx.x * blockDim.x + threadIdx.x;
    if (idx >= RTHREADS) return;

    int face = idx / TPF;
    int t    = idx - face * TPF;
    int ky   = t / 3;
    int kx0  = (t - ky * 3) * 4;

    RRec rec = g_rrec[face];
    if (!rec.valid) return;

    int n  = face / NF;
    int fl = face - n * NF;
    int rbase = fl * FRAGS + ky * KK;            /* cand index base */

    int py = rec.bcy + ky;
    float pyf = (float)py;
    float dy1 = __fsub_rn(pyf, rec.y1);
    float dy2 = __fsub_rn(pyf, rec.y2);
    float t0  = __fmul_rn(rec.A0, dy1);          /* c0 = t0 - B0*(px-x1) */
    float t1  = __fmul_rn(rec.A1, dy2);          /* c1 = t1 - B1*(px-x2) */

    unsigned long long* zrow = g_zkey + n * (HH*WW) + py * WW;

    #pragma unroll
    for (int j = 0; j < 4; j++) {
        int kx = kx0 + j;
        int px = rec.bcx + kx;
        float pxf = (float)px;

        float c0 = __fsub_rn(t0, __fmul_rn(rec.B0, __fsub_rn(pxf, rec.x1)));
        float c1 = __fsub_rn(t1, __fmul_rn(rec.B1, __fsub_rn(pxf, rec.x2)));

        /* conservative exact sign early-out (c==+/-0 never rejected) */
        if (__fmul_rn(c0, rec.area) < 0.f || __fmul_rn(c1, rec.area) < 0.f)
            continue;

        float w0 = div_full(c0, rec.area);
        float w1 = div_full(c1, rec.area);
        float w2 = __fsub_rn(__fsub_rn(1.0f, w0), w1);

        if (!(w0 >= 0.f && w1 >= 0.f && w2 >= 0.f)) continue;

        float depth = lerp3(w0, rec.z0, w1, rec.z1, w2, rec.z2);

        unsigned long long key =
            ((unsigned long long)__float_as_uint(depth) << 32) |
            (unsigned int)(rbase + kx);
        atomicMin(&zrow[px], key);
    }
}

__global__ void __launch_bounds__(256) resolve_kernel(float* __restrict__ out) {
    int i = blockIdx.x * blockDim.x + threadIdx.x;
    if (i >= NPIX) return;

    int n = i / (HH*WW);
    int p = i - n * (HH*WW);

    unsigned long long key = g_zkey[i];
    float u = 0.f, v = 0.f;
    bool has = (key != 0xFFFFFFFFFFFFFFFFULL);

    if (has) {
        int r   = (int)(key & 0xFFFFFFFFu);
        int f   = r / FRAGS;
        int rem = r - f * FRAGS;
        int ky  = rem / KK;
        int kx  = rem - ky * KK;

        int face = n * NF + f;
        RRec  rec = g_rrec[face];
        UVRec uv  = g_uv[face];

        float pxf = (float)(rec.bcx + kx);
        float pyf = (float)(rec.bcy + ky);

        float c0 = __fsub_rn(__fmul_rn(rec.A0, __fsub_rn(pyf, rec.y1)),
                             __fmul_rn(rec.B0, __fsub_rn(pxf, rec.x1)));
        float c1 = __fsub_rn(__fmul_rn(rec.A1, __fsub_rn(pyf, rec.y2)),
                             __fmul_rn(rec.B1, __fsub_rn(pxf, rec.x2)));

        float w0 = div_full(c0, rec.area);
        float w1 = div_full(c1, rec.area);
        float w2 = __fsub_rn(__fsub_rn(1.0f, w0), w1);

        u = lerp3(w0, uv.u0, w1, uv.u1, w2, uv.u2);
        v = lerp3(w0, uv.v0, w1, uv.v1, w2, uv.v2);
    }

    float mask = (has && (u > 0.f || v > 0.f)) ? 1.0f : 0.0f;

    float ou, ov;
    if (mask > 0.f) {
        ou = __fsub_rn(__fmul_rn(u, 2.0f), 1.0f);
        ov = __fsub_rn(__fmul_rn(v, 2.0f), 1.0f);
    } else {
        ou = -10.0f;
        ov = -10.0f;
    }

    size_t hw = (size_t)HH * WW;
    out[((size_t)n * 2 + 0) * hw + p] = ou;
    out[((size_t)n * 2 + 1) * hw + p] = ov;
    out[(size_t)NB * 2 * hw + (size_t)n * hw + p] = mask;
}

extern "C" void kernel_launch(void* const* d_in, const int* in_sizes, int n_in,
                              void* d_out, int out_size) {
    const float* verts = (const float*)d_in[0];
    const int*   faces = (const int*)d_in[1];
    const float* vals  = (const float*)d_in[2];
    float* out = (float*)d_out;

    init_kernel<<<(NPIX/2 + 255) / 256, 256>>>();
    setup_kernel<<<(NFACE + 255) / 256, 256>>>(verts, faces, vals);
    raster_kernel<<<(RTHREADS + 255) / 256, 256>>>();
    resolve_kernel<<<(NPIX + 255) / 256, 256>>>(out);
}

// round 6
// speedup vs baseline: 1.5271x; 1.1208x over previous
#include <cuda_runtime.h>
#include <cstdint>

#define HH 512
#define WW 512
#define GG 83
#define KK 12
#define NB 8
#define NF (2*(GG-1)*(GG-1))      /* 13448 faces */
#define NV (GG*GG)                /* 6889 verts  */
#define FRAGS (KK*KK)             /* 144         */
#define NFACE (NB*NF)             /* 107,584     */
#define NPIX (NB*HH*WW)           /* 2,097,152   */

#define RROWS (NFACE*KK)          /* raster threads: one per (face,row) */
#define PREPT (NPIX/2)            /* prep threads: one 16B zkey store each */

struct __align__(16) RRec {
    float A0, B0, x1, y1;    /* c0 = A0*(py-y1) - B0*(px-x1), A0=x2-x1, B0=y2-y1 */
    float A1, B1, x2, y2;    /* c1 = A1*(py-y2) - B1*(px-x2), A1=x0-x2, B1=y0-y2 */
    float area, z0, z1, z2;
    int bcx, bcy, valid, pad;
};

struct __align__(16) UVRec {
    float u0, v0, u1, v1;
    float u2, v2, p0, p1;
};

__device__ RRec  g_rrec[NFACE];
__device__ UVRec g_uv[NFACE];
__device__ unsigned long long g_zkey[NPIX];

/* XLA:GPU f32 division (NVPTX div.full: fast, ~2ulp, sign-correct) */
__device__ __forceinline__ float div_full(float a, float b) {
    float r;
    asm("div.full.f32 %0, %1, %2;" : "=f"(r) : "f"(a), "f"(b));
    return r;
}

/* Unfused a*b - c*d, matching jnp elementwise evaluation */
__device__ __forceinline__ float edge_fn(float ax, float ay, float bx, float by) {
    return __fsub_rn(__fmul_rn(ax, ay), __fmul_rn(bx, by));
}

/* Unfused w0*a + w1*b + w2*c, left-associated */
__device__ __forceinline__ float lerp3(float w0, float a, float w1, float b,
                                       float w2, float c) {
    return __fadd_rn(__fadd_rn(__fmul_rn(w0, a), __fmul_rn(w1, b)),
                     __fmul_rn(w2, c));
}

/* init zkey (all threads) + per-face setup (first NFACE threads) */
__global__ void __launch_bounds__(256) prep_kernel(const float* __restrict__ verts,
                                                   const int*   __restrict__ faces,
                                                   const float* __restrict__ vals) {
    int idx = blockIdx.x * blockDim.x + threadIdx.x;
    if (idx < PREPT) {
        ((ulonglong2*)g_zkey)[idx] =
            make_ulonglong2(0xFFFFFFFFFFFFFFFFULL, 0xFFFFFFFFFFFFFFFFULL);
    }
    if (idx >= NFACE) return;

    int n = idx / NF;
    int f = idx - n * NF;

    int i0 = faces[3*f + 0];
    int i1 = faces[3*f + 1];
    int i2 = faces[3*f + 2];

    const float* vb = verts + (size_t)n * NV * 3;
    float z0 = vb[3*i0+2], z1 = vb[3*i1+2], z2 = vb[3*i2+2];

    /* projection via div.full, matching XLA:GPU p = v[:,:2] / z */
    float x0 = div_full(vb[3*i0+0], z0), y0 = div_full(vb[3*i0+1], z0);
    float x1 = div_full(vb[3*i1+0], z1), y1 = div_full(vb[3*i1+1], z1);
    float x2 = div_full(vb[3*i2+0], z2), y2 = div_full(vb[3*i2+1], z2);

    float minx = floorf(fminf(fminf(x0, x1), x2));
    float miny = floorf(fminf(fminf(y0, y1), y2));
    int bcx = (int)fminf(fmaxf(minx, 0.f), (float)(WW - KK));
    int bcy = (int)fminf(fmaxf(miny, 0.f), (float)(HH - KK));

    float area = edge_fn(__fsub_rn(x1,x0), __fsub_rn(y2,y0),
                         __fsub_rn(y1,y0), __fsub_rn(x2,x0));

    bool front = (z0 > 0.f && z1 > 0.f && z2 > 0.f);
    bool valid = front && (fabsf(area) > 1e-9f);

    RRec rec;
    rec.A0 = __fsub_rn(x2, x1); rec.B0 = __fsub_rn(y2, y1);
    rec.x1 = x1; rec.y1 = y1;
    rec.A1 = __fsub_rn(x0, x2); rec.B1 = __fsub_rn(y0, y2);
    rec.x2 = x2; rec.y2 = y2;
    rec.area = area;
    rec.z0 = z0; rec.z1 = z1; rec.z2 = z2;
    rec.bcx = bcx; rec.bcy = bcy;
    rec.valid = valid ? 1 : 0;
    rec.pad = 0;
    g_rrec[idx] = rec;

    UVRec uv;
    uv.u0 = vals[2*i0+0]; uv.v0 = vals[2*i0+1];
    uv.u1 = vals[2*i1+0]; uv.v1 = vals[2*i1+1];
    uv.u2 = vals[2*i2+0]; uv.v2 = vals[2*i2+1];
    uv.p0 = 0.f; uv.p1 = 0.f;
    g_uv[idx] = uv;
}

__global__ void __launch_bounds__(256) raster_kernel() {
    int idx = blockIdx.x * blockDim.x + threadIdx.x;
    if (idx >= RROWS) return;

    int face = idx / KK;
    int ky   = idx - face * KK;

    RRec rec = g_rrec[face];
    if (!rec.valid) return;

    /* approximate v0 position (within ~1e-4 of true x0/y0; bounds use 0.01 guard) */
    float x0r = __fadd_rn(rec.x2, rec.A1);
    float y0r = __fadd_rn(rec.y2, rec.B1);

    int py = rec.bcy + ky;
    float pyf = (float)py;

    /* exact-geometry row cull: float edge tests cannot pass >1e-3 px outside */
    float ymin = fminf(fminf(rec.y1, rec.y2), y0r);
    float ymax = fmaxf(fmaxf(rec.y1, rec.y2), y0r);
    if (pyf < ymin - 0.01f || pyf > ymax + 0.01f) return;

    float xmin = fminf(fminf(rec.x1, rec.x2), x0r);
    float xmax = fmaxf(fmaxf(rec.x1, rec.x2), x0r);
    int lo = max(0,      (int)ceilf (xmin - 0.01f) - rec.bcx);
    int hi = min(KK - 1, (int)floorf(xmax + 0.01f) - rec.bcx);
    if (lo > hi) return;

    int n  = face / NF;
    int fl = face - n * NF;
    int rbase = fl * FRAGS + ky * KK;            /* cand index base */

    float t0 = __fmul_rn(rec.A0, __fsub_rn(pyf, rec.y1));
    float t1 = __fmul_rn(rec.A1, __fsub_rn(pyf, rec.y2));

    unsigned long long* zrow = g_zkey + n * (HH*WW) + py * WW;

    for (int kx = lo; kx <= hi; kx++) {
        int px = rec.bcx + kx;
        float pxf = (float)px;

        float c0 = __fsub_rn(t0, __fmul_rn(rec.B0, __fsub_rn(pxf, rec.x1)));
        float c1 = __fsub_rn(t1, __fmul_rn(rec.B1, __fsub_rn(pxf, rec.x2)));

        /* conservative sign early-out (c==+/-0 never rejected) */
        if (__fmul_rn(c0, rec.area) < 0.f || __fmul_rn(c1, rec.area) < 0.f)
            continue;

        float w0 = div_full(c0, rec.area);
        float w1 = div_full(c1, rec.area);
        float w2 = __fsub_rn(__fsub_rn(1.0f, w0), w1);

        if (!(w0 >= 0.f && w1 >= 0.f && w2 >= 0.f)) continue;

        float depth = lerp3(w0, rec.z0, w1, rec.z1, w2, rec.z2);

        unsigned long long key =
            ((unsigned long long)__float_as_uint(depth) << 32) |
            (unsigned int)(rbase + kx);
        atomicMin(&zrow[px], key);
    }
}

__device__ __forceinline__ void resolve_pixel(unsigned long long key, int n, int p,
                                              float& ou, float& ov, float& om) {
    float u = 0.f, v = 0.f;
    bool has = (key != 0xFFFFFFFFFFFFFFFFULL);

    if (has) {
        int r   = (int)(key & 0xFFFFFFFFu);
        int f   = r / FRAGS;
        int rem = r - f * FRAGS;
        int ky  = rem / KK;
        int kx  = rem - ky * KK;

        int face = n * NF + f;
        RRec  rec = g_rrec[face];
        UVRec uv  = g_uv[face];

        float pxf = (float)(rec.bcx + kx);
        float pyf = (float)(rec.bcy + ky);

        float c0 = __fsub_rn(__fmul_rn(rec.A0, __fsub_rn(pyf, rec.y1)),
                             __fmul_rn(rec.B0, __fsub_rn(pxf, rec.x1)));
        float c1 = __fsub_rn(__fmul_rn(rec.A1, __fsub_rn(pyf, rec.y2)),
                             __fmul_rn(rec.B1, __fsub_rn(pxf, rec.x2)));

        float w0 = div_full(c0, rec.area);
        float w1 = div_full(c1, rec.area);
        float w2 = __fsub_rn(__fsub_rn(1.0f, w0), w1);

        u = lerp3(w0, uv.u0, w1, uv.u1, w2, uv.u2);
        v = lerp3(w0, uv.v0, w1, uv.v1, w2, uv.v2);
    }

    float mask = (has && (u > 0.f || v > 0.f)) ? 1.0f : 0.0f;
    if (mask > 0.f) {
        ou = __fsub_rn(__fmul_rn(u, 2.0f), 1.0f);
        ov = __fsub_rn(__fmul_rn(v, 2.0f), 1.0f);
    } else {
        ou = -10.0f;
        ov = -10.0f;
    }
    om = mask;
}

__global__ void __launch_bounds__(256) resolve_kernel(float* __restrict__ out) {
    int i = blockIdx.x * blockDim.x + threadIdx.x;   /* 2 pixels per thread */
    if (i >= NPIX / 2) return;

    int pp = 2 * i;
    int n  = pp / (HH*WW);
    int p  = pp - n * (HH*WW);

    ulonglong2 k2 = ((const ulonglong2*)g_zkey)[i];

    float ou0, ov0, om0, ou1, ov1, om1;
    resolve_pixel(k2.x, n, p,     ou0, ov0, om0);
    resolve_pixel(k2.y, n, p + 1, ou1, ov1, om1);

    size_t hw = (size_t)HH * WW;
    float* ru = out + ((size_t)n * 2 + 0) * hw + p;
    float* rv = out + ((size_t)n * 2 + 1) * hw + p;
    float* rm = out + (size_t)NB * 2 * hw + (size_t)n * hw + p;
    *(float2*)ru = make_float2(ou0, ou1);
    *(float2*)rv = make_float2(ov0, ov1);
    *(float2*)rm = make_float2(om0, om1);
}

extern "C" void kernel_launch(void* const* d_in, const int* in_sizes, int n_in,
                              void* d_out, int out_size) {
    const float* verts = (const float*)d_in[0];
    const int*   faces = (const int*)d_in[1];
    const float* vals  = (const float*)d_in[2];
    float* out = (float*)d_out;

    prep_kernel<<<(PREPT + 255) / 256, 256>>>(verts, faces, vals);
    raster_kernel<<<(RROWS + 255) / 256, 256>>>();
    resolve_kernel<<<(NPIX/2 + 255) / 256, 256>>>(out);
}